// round 1
// baseline (speedup 1.0000x reference)
#include <cuda_runtime.h>

#define BB 4
#define CC 256
#define HH 128
#define WW 128
#define HWD (HH*WW)
#define NHEAD 8
#define DK 64
#define CO 512
#define KER 7
#define RAD 3
#define NN 49
#define LN_EPS 1e-6f

#define TW 16
#define TH 8
#define HLW (TW + 2*RAD)   // 22
#define HLH (TH + 2*RAD)   // 14
#define NPOS (HLW*HLH)     // 308

// ---------------- scratch (device globals: allowed; no cudaMalloc) ----------------
__device__ float g_qh[33554432];   // [B][512][HW] q-proj; reused as FC output later
__device__ float g_kh[33554432];   // [B][512][HW]
__device__ float g_vh[33554432];   // [B][512][HW]
__device__ float g_att[33554432];  // [B][512][HW] attention output

__device__ __forceinline__ unsigned long long dup2(float x) {
    unsigned int u = __float_as_uint(x);
    return ((unsigned long long)u << 32) | (unsigned long long)u;
}

// ---------------- GEMM: Y[b][m][p] = sum_k W[m][k] * X[b][k][p] ----------------
// Block tile 128(m) x 128(p), K-chunk 8, 256 threads, 8x8 per-thread tile.
// Accumulators are packed f32x2 (FFMA2) -> 2x fp32 FMA throughput on sm_103a.
__global__ __launch_bounds__(256, 1)
void gemm_kernel(const float* __restrict__ Wg, const float* __restrict__ Xg,
                 float* __restrict__ Yg, int M, int K)
{
    __shared__ unsigned long long As2[8][128];  // A values duplicated into both f32x2 lanes
    __shared__ float Bs[8][128];

    const int b  = blockIdx.z;
    const int n0 = blockIdx.x * 128;
    const int m0 = blockIdx.y * 128;
    const float* X = Xg + (size_t)b * K * HWD;
    float* Y = Yg + (size_t)b * M * HWD;

    const int tid = threadIdx.x;
    const int tm = (tid >> 4) * 8;
    const int tn = (tid & 15) * 8;

    const int arow = tid >> 1;        // 0..127
    const int acol = (tid & 1) * 4;   // 0 or 4
    const int brow = tid >> 5;        // 0..7
    const int bcol = (tid & 31) * 4;  // 0..124

    unsigned long long acc[8][4];
#pragma unroll
    for (int i = 0; i < 8; i++)
#pragma unroll
        for (int j = 0; j < 4; j++) acc[i][j] = 0ULL;

    const float* wptr = Wg + (size_t)(m0 + arow) * K + acol;
    const float* xptr = X + (size_t)brow * HWD + n0 + bcol;

    for (int k0 = 0; k0 < K; k0 += 8) {
        float4 av = *(const float4*)(wptr + k0);
        float4 bv = *(const float4*)(xptr + (size_t)k0 * HWD);
        __syncthreads();
        As2[acol + 0][arow] = dup2(av.x);
        As2[acol + 1][arow] = dup2(av.y);
        As2[acol + 2][arow] = dup2(av.z);
        As2[acol + 3][arow] = dup2(av.w);
        *(float4*)&Bs[brow][bcol] = bv;
        __syncthreads();
#pragma unroll
        for (int kk = 0; kk < 8; kk++) {
            unsigned long long a[8], bb2[4];
#pragma unroll
            for (int i = 0; i < 8; i++) a[i] = As2[kk][tm + i];
            const unsigned long long* bp = (const unsigned long long*)&Bs[kk][tn];
#pragma unroll
            for (int j = 0; j < 4; j++) bb2[j] = bp[j];
#pragma unroll
            for (int i = 0; i < 8; i++)
#pragma unroll
                for (int j = 0; j < 4; j++)
                    asm("fma.rn.f32x2 %0, %1, %2, %0;"
                        : "+l"(acc[i][j]) : "l"(a[i]), "l"(bb2[j]));
        }
    }

#pragma unroll
    for (int i = 0; i < 8; i++) {
        unsigned long long* yp =
            (unsigned long long*)(Y + (size_t)(m0 + tm + i) * HWD + n0 + tn);
#pragma unroll
        for (int j = 0; j < 4; j++) yp[j] = acc[i][j];
    }
}

// ---------------- Local windowed attention ----------------
// One CTA = one head x one 16x8 pixel tile. k/v halo tiles in dynamic smem,
// layout [c][pos] (pos contiguous) for conflict-free LDS across the warp.
__global__ __launch_bounds__(128, 1)
void attn_kernel(const float* __restrict__ qh, const float* __restrict__ kh,
                 const float* __restrict__ vh, float* __restrict__ outp)
{
    extern __shared__ float sm[];
    float* ks = sm;                // [DK][NPOS]
    float* vs = sm + DK * NPOS;    // [DK][NPOS]

    const int tid = threadIdx.x;
    const int bz = blockIdx.z;
    const int b = bz >> 3;
    const int h = bz & 7;
    const int x0 = blockIdx.x * TW - RAD;
    const int y0 = blockIdx.y * TH - RAD;

    const size_t hbase = ((size_t)b * CO + (size_t)h * DK) * HWD;
    const float* kb = kh + hbase;
    const float* vb = vh + hbase;

    // fill halo (zero padding outside the image)
    for (int c = 0; c < DK; c++) {
        size_t cg = (size_t)c * HWD;
        for (int pos = tid; pos < NPOS; pos += 128) {
            int yy = y0 + pos / HLW;
            int xx = x0 + pos % HLW;
            float kv = 0.f, vv = 0.f;
            if (yy >= 0 && yy < HH && xx >= 0 && xx < WW) {
                size_t g = cg + (size_t)yy * WW + xx;
                kv = kb[g];
                vv = vb[g];
            }
            ks[c * NPOS + pos] = kv;
            vs[c * NPOS + pos] = vv;
        }
    }
    __syncthreads();

    const int tx = tid & 15;
    const int ty = tid >> 4;
    const int gx = blockIdx.x * TW + tx;
    const int gy = blockIdx.y * TH + ty;
    const size_t pbase = hbase + (size_t)gy * WW + gx;
    const int sbase = ty * HLW + tx;

    float sc[NN];
#pragma unroll
    for (int d = 0; d < NN; d++) sc[d] = 0.f;

    // phase 1: correlation scores (q dot k over 64 channels, 49 neighbors)
    for (int c0 = 0; c0 < DK; c0 += 8) {
        float qv[8];
#pragma unroll
        for (int j = 0; j < 8; j++) qv[j] = qh[pbase + (size_t)(c0 + j) * HWD];
#pragma unroll
        for (int j = 0; j < 8; j++) {
            const float* kr = ks + (c0 + j) * NPOS + sbase;
#pragma unroll
            for (int dy = 0; dy < KER; dy++)
#pragma unroll
                for (int dx = 0; dx < KER; dx++)
                    sc[dy * KER + dx] = fmaf(qv[j], kr[dy * HLW + dx], sc[dy * KER + dx]);
        }
    }

    // softmax over 49 neighbors, temperature = sqrt(64) = 8
    const float invT = 0.125f;
    float mx = sc[0];
#pragma unroll
    for (int d = 1; d < NN; d++) mx = fmaxf(mx, sc[d]);
    float ssum = 0.f;
#pragma unroll
    for (int d = 0; d < NN; d++) {
        float e = expf((sc[d] - mx) * invT);
        sc[d] = e;
        ssum += e;
    }
    float rinv = 1.f / ssum;
#pragma unroll
    for (int d = 0; d < NN; d++) sc[d] *= rinv;

    // phase 2: weighted sum of v over the same neighborhood
    for (int c0 = 0; c0 < DK; c0 += 4) {
        float acc[4] = {0.f, 0.f, 0.f, 0.f};
#pragma unroll
        for (int j = 0; j < 4; j++) {
            const float* vr = vs + (c0 + j) * NPOS + sbase;
#pragma unroll
            for (int dy = 0; dy < KER; dy++)
#pragma unroll
                for (int dx = 0; dx < KER; dx++)
                    acc[j] = fmaf(sc[dy * KER + dx], vr[dy * HLW + dx], acc[j]);
        }
#pragma unroll
        for (int j = 0; j < 4; j++)
            outp[pbase + (size_t)(c0 + j) * HWD] = acc[j];
    }
}

// ---------------- residual + LayerNorm2d (over channel dim) ----------------
__global__ __launch_bounds__(256)
void ln_kernel(const float* __restrict__ fc, const float* __restrict__ res,
               const float* __restrict__ lnw, const float* __restrict__ lnb,
               float* __restrict__ out)
{
    int p = blockIdx.x * 256 + threadIdx.x;   // 0 .. B*HWD-1
    int b = p / HWD;
    int pp = p - b * HWD;
    const float* f = fc + (size_t)b * CC * HWD + pp;
    const float* r = res + (size_t)b * CC * HWD + pp;

    float s = 0.f, s2 = 0.f;
#pragma unroll 4
    for (int c = 0; c < CC; c++) {
        float v = f[(size_t)c * HWD] + r[(size_t)c * HWD];
        s += v;
        s2 = fmaf(v, v, s2);
    }
    float mu = s * (1.f / CC);
    float var = s2 * (1.f / CC) - mu * mu;
    float inv = rsqrtf(var + LN_EPS);

    float* o = out + (size_t)b * CC * HWD + pp;
#pragma unroll 4
    for (int c = 0; c < CC; c++) {
        float v = f[(size_t)c * HWD] + r[(size_t)c * HWD];
        o[(size_t)c * HWD] = lnw[c] * ((v - mu) * inv) + lnb[c];
    }
}

// ---------------- launch ----------------
extern "C" void kernel_launch(void* const* d_in, const int* in_sizes, int n_in,
                              void* d_out, int out_size)
{
    const float* q   = (const float*)d_in[0];
    const float* k   = (const float*)d_in[1];
    const float* v   = (const float*)d_in[2];
    const float* Wq  = (const float*)d_in[3];
    const float* Wk  = (const float*)d_in[4];
    const float* Wv  = (const float*)d_in[5];
    const float* Wfc = (const float*)d_in[6];
    const float* lnw = (const float*)d_in[7];
    const float* lnb = (const float*)d_in[8];
    // d_in[9], d_in[10] = kernel(7), pad(3): compile-time constants here

    float *qh, *kh, *vh, *att;
    cudaGetSymbolAddress((void**)&qh, g_qh);
    cudaGetSymbolAddress((void**)&kh, g_kh);
    cudaGetSymbolAddress((void**)&vh, g_vh);
    cudaGetSymbolAddress((void**)&att, g_att);
    float* fcb = qh;  // reuse q-proj scratch for FC output (qh dead after attention)

    // 1) projections: [512,256] x [256,16384] per batch
    dim3 gp(HWD / 128, CO / 128, BB);
    gemm_kernel<<<gp, 256>>>(Wq, q, qh, CO, CC);
    gemm_kernel<<<gp, 256>>>(Wk, k, kh, CO, CC);
    gemm_kernel<<<gp, 256>>>(Wv, v, vh, CO, CC);

    // 2) local attention
    int smem = 2 * DK * NPOS * (int)sizeof(float);  // ~158 KB
    cudaFuncSetAttribute(attn_kernel, cudaFuncAttributeMaxDynamicSharedMemorySize, smem);
    dim3 ga(WW / TW, HH / TH, BB * NHEAD);
    attn_kernel<<<ga, 128, smem>>>(qh, kh, vh, att);

    // 3) output projection: [256,512] x [512,16384] per batch
    dim3 gf(HWD / 128, CC / 128, BB);
    gemm_kernel<<<gf, 256>>>(Wfc, att, fcb, CC, CO);

    // 4) residual + LayerNorm over channels
    ln_kernel<<<(BB * HWD) / 256, 256>>>(fcb, q, lnw, lnb, (float*)d_out);
}

// round 2
// speedup vs baseline: 1.2809x; 1.2809x over previous
#include <cuda_runtime.h>

#define BB 4
#define CC 256
#define HH 128
#define WW 128
#define HWD (HH*WW)
#define NHEAD 8
#define DK 64
#define CO 512
#define KER 7
#define RAD 3
#define NN 49
#define LN_EPS 1e-6f

// attention tile
#define ATW 32
#define ATH 16
#define AHLW (ATW + 2*RAD)   // 38
#define AHLH (ATH + 2*RAD)   // 22
#define ANPOS (AHLW*AHLH)    // 836

// ---------------- scratch (device globals: allowed; no cudaMalloc) ----------------
__device__ float g_qh[33554432];   // [B][512][HW] q-proj; reused as FC output later
__device__ float g_kh[33554432];   // [B][512][HW]
__device__ float g_vh[33554432];   // [B][512][HW]
__device__ float g_att[33554432];  // [B][512][HW] attention output

__device__ __forceinline__ unsigned long long dup2(float x) {
    unsigned int u = __float_as_uint(x);
    return ((unsigned long long)u << 32) | (unsigned long long)u;
}

// ---------------- GEMM: Y[b][m][p] = sum_k W[m][k] * X[b][k][p] ----------------
// 128x128 tile, bk=16, ping-pong smem (1 sync/chunk), register prefetch,
// packed-f32x2 accumulators (FFMA2), 2 CTAs/SM.
__global__ __launch_bounds__(256, 2)
void gemm_kernel(const float* __restrict__ Wg, const float* __restrict__ Xg,
                 float* __restrict__ Yg, int M, int K)
{
    extern __shared__ char gsm[];
    typedef unsigned long long u64;
    u64   (*As2)[16][128] = (u64 (*)[16][128])gsm;                 // 2 x 16KB
    float (*Bs )[16][128] = (float (*)[16][128])(gsm + 2*16*128*8); // 2 x 8KB

    const int b  = blockIdx.z;
    const int n0 = blockIdx.x * 128;
    const int m0 = blockIdx.y * 128;
    const float* X = Xg + (size_t)b * K * HWD;
    float* Y = Yg + (size_t)b * M * HWD;

    const int tid = threadIdx.x;
    const int tm = (tid >> 4) * 8;
    const int tn = (tid & 15) * 8;

    const int arow = tid >> 1;        // 0..127
    const int acol = (tid & 1) * 8;   // 0 or 8
    const int brow = tid >> 4;        // 0..15
    const int bcol = (tid & 15) * 8;  // 0..120

    const float* wp = Wg + (size_t)(m0 + arow) * K + acol;
    const float* xp = X + (size_t)brow * HWD + n0 + bcol;

    u64 acc[8][4];
#pragma unroll
    for (int i = 0; i < 8; i++)
#pragma unroll
        for (int j = 0; j < 4; j++) acc[i][j] = 0ULL;

    // prefetch chunk 0
    float4 ra0 = *(const float4*)(wp);
    float4 ra1 = *(const float4*)(wp + 4);
    float4 rb0 = *(const float4*)(xp);
    float4 rb1 = *(const float4*)(xp + 4);

    // store chunk 0 into buf 0
    {
        As2[0][acol+0][arow] = dup2(ra0.x);
        As2[0][acol+1][arow] = dup2(ra0.y);
        As2[0][acol+2][arow] = dup2(ra0.z);
        As2[0][acol+3][arow] = dup2(ra0.w);
        As2[0][acol+4][arow] = dup2(ra1.x);
        As2[0][acol+5][arow] = dup2(ra1.y);
        As2[0][acol+6][arow] = dup2(ra1.z);
        As2[0][acol+7][arow] = dup2(ra1.w);
        *(float4*)&Bs[0][brow][bcol]   = rb0;
        *(float4*)&Bs[0][brow][bcol+4] = rb1;
    }
    __syncthreads();

    const int nc = K >> 4;
    for (int ch = 0; ch < nc; ch++) {
        const int cur = ch & 1;
        if (ch + 1 < nc) {
            const float* w2 = wp + (ch + 1) * 16;
            const float* x2 = xp + (size_t)(ch + 1) * 16 * HWD;
            ra0 = *(const float4*)(w2);
            ra1 = *(const float4*)(w2 + 4);
            rb0 = *(const float4*)(x2);
            rb1 = *(const float4*)(x2 + 4);
        }
#pragma unroll
        for (int kk = 0; kk < 16; kk++) {
            u64 a[8], bb2[4];
#pragma unroll
            for (int i = 0; i < 8; i++) a[i] = As2[cur][kk][tm + i];
            const u64* bp = (const u64*)&Bs[cur][kk][tn];
#pragma unroll
            for (int j = 0; j < 4; j++) bb2[j] = bp[j];
#pragma unroll
            for (int i = 0; i < 8; i++)
#pragma unroll
                for (int j = 0; j < 4; j++)
                    asm("fma.rn.f32x2 %0, %1, %2, %0;"
                        : "+l"(acc[i][j]) : "l"(a[i]), "l"(bb2[j]));
        }
        if (ch + 1 < nc) {
            const int nxt = cur ^ 1;   // safe: peers read buf[cur], we write buf[nxt]
            As2[nxt][acol+0][arow] = dup2(ra0.x);
            As2[nxt][acol+1][arow] = dup2(ra0.y);
            As2[nxt][acol+2][arow] = dup2(ra0.z);
            As2[nxt][acol+3][arow] = dup2(ra0.w);
            As2[nxt][acol+4][arow] = dup2(ra1.x);
            As2[nxt][acol+5][arow] = dup2(ra1.y);
            As2[nxt][acol+6][arow] = dup2(ra1.z);
            As2[nxt][acol+7][arow] = dup2(ra1.w);
            *(float4*)&Bs[nxt][brow][bcol]   = rb0;
            *(float4*)&Bs[nxt][brow][bcol+4] = rb1;
            __syncthreads();
        }
    }

#pragma unroll
    for (int i = 0; i < 8; i++) {
        u64* yp = (u64*)(Y + (size_t)(m0 + tm + i) * HWD + n0 + tn);
#pragma unroll
        for (int j = 0; j < 4; j++) yp[j] = acc[i][j];
    }
}

// ---------------- Local windowed attention (v2) ----------------
// Tile 32x16 px, 256 threads (8 warps). Warp = one 32-wide row -> every LDS is
// 32 consecutive words: conflict-free. Each thread owns 2 vertically-adjacent
// pixels; their 7x7 windows share 6 of 8 halo rows, so each k-row register
// load serves both pixels (1.75x fewer smem bytes). k then v phases reuse one
// 214KB halo buffer.
__global__ __launch_bounds__(256, 1)
void attn_kernel(const float* __restrict__ qh, const float* __restrict__ kh,
                 const float* __restrict__ vh, float* __restrict__ outp)
{
    extern __shared__ float sm[];   // [DK][ANPOS]

    const int tid = threadIdx.x;
    const int bz = blockIdx.z;
    const int b = bz >> 3;
    const int h = bz & 7;
    const int x0 = blockIdx.x * ATW - RAD;
    const int y0 = blockIdx.y * ATH - RAD;
    const size_t hbase = ((size_t)b * CO + (size_t)h * DK) * HWD;

    // ---- fill K halo ----
    {
        const float* kb = kh + hbase;
        for (int c = 0; c < DK; c++) {
            const float* kc = kb + (size_t)c * HWD;
            float* s = sm + c * ANPOS;
            for (int pos = tid; pos < ANPOS; pos += 256) {
                int hy = pos / AHLW;
                int hx = pos - hy * AHLW;
                int yy = y0 + hy, xx = x0 + hx;
                float v = 0.f;
                if ((unsigned)yy < HH && (unsigned)xx < WW)
                    v = kc[yy * WW + xx];
                s[pos] = v;
            }
        }
    }
    __syncthreads();

    const int tx = tid & 31;
    const int ty = tid >> 5;                  // 0..7 (row-pair index)
    const int gx = blockIdx.x * ATW + tx;
    const int gy = blockIdx.y * ATH + 2 * ty; // px0 row; px1 = gy+1
    const size_t pbase = hbase + (size_t)gy * WW + gx;
    const int sb = (2 * ty) * AHLW + tx;      // halo offset: window row rr=0, col dx=0

    float sc0[NN], sc1[NN];
#pragma unroll
    for (int d = 0; d < NN; d++) { sc0[d] = 0.f; sc1[d] = 0.f; }

    // ---- phase 1: correlation scores ----
    for (int c = 0; c < DK; c++) {
        float q0 = qh[pbase + (size_t)c * HWD];
        float q1 = qh[pbase + WW + (size_t)c * HWD];
        const float* kc = sm + c * ANPOS + sb;
#pragma unroll
        for (int rr = 0; rr < 8; rr++) {
            float kw[KER];
#pragma unroll
            for (int j = 0; j < KER; j++) kw[j] = kc[rr * AHLW + j];
            if (rr < 7) {
#pragma unroll
                for (int dx = 0; dx < KER; dx++)
                    sc0[rr * KER + dx] = fmaf(q0, kw[dx], sc0[rr * KER + dx]);
            }
            if (rr >= 1) {
#pragma unroll
                for (int dx = 0; dx < KER; dx++)
                    sc1[(rr - 1) * KER + dx] = fmaf(q1, kw[dx], sc1[(rr - 1) * KER + dx]);
            }
        }
    }
    __syncthreads();   // done reading k halo

    // ---- fill V halo (same buffer) ----
    {
        const float* vb = vh + hbase;
        for (int c = 0; c < DK; c++) {
            const float* vc = vb + (size_t)c * HWD;
            float* s = sm + c * ANPOS;
            for (int pos = tid; pos < ANPOS; pos += 256) {
                int hy = pos / AHLW;
                int hx = pos - hy * AHLW;
                int yy = y0 + hy, xx = x0 + hx;
                float v = 0.f;
                if ((unsigned)yy < HH && (unsigned)xx < WW)
                    v = vc[yy * WW + xx];
                s[pos] = v;
            }
        }
    }

    // ---- softmax (register-local; overlaps fill latency) ----
    {
        const float invT = 0.125f;   // 1/sqrt(64)
        float mx0 = sc0[0], mx1 = sc1[0];
#pragma unroll
        for (int d = 1; d < NN; d++) { mx0 = fmaxf(mx0, sc0[d]); mx1 = fmaxf(mx1, sc1[d]); }
        float s0 = 0.f, s1 = 0.f;
#pragma unroll
        for (int d = 0; d < NN; d++) {
            float e0 = expf((sc0[d] - mx0) * invT);
            float e1 = expf((sc1[d] - mx1) * invT);
            sc0[d] = e0; sc1[d] = e1;
            s0 += e0; s1 += e1;
        }
        float r0 = 1.f / s0, r1 = 1.f / s1;
#pragma unroll
        for (int d = 0; d < NN; d++) { sc0[d] *= r0; sc1[d] *= r1; }
    }
    __syncthreads();   // v halo ready

    // ---- phase 2: weighted sum of v ----
    for (int c = 0; c < DK; c++) {
        const float* vc = sm + c * ANPOS + sb;
        float a0 = 0.f, a1 = 0.f;
#pragma unroll
        for (int rr = 0; rr < 8; rr++) {
            float kw[KER];
#pragma unroll
            for (int j = 0; j < KER; j++) kw[j] = vc[rr * AHLW + j];
            if (rr < 7) {
#pragma unroll
                for (int dx = 0; dx < KER; dx++)
                    a0 = fmaf(sc0[rr * KER + dx], kw[dx], a0);
            }
            if (rr >= 1) {
#pragma unroll
                for (int dx = 0; dx < KER; dx++)
                    a1 = fmaf(sc1[(rr - 1) * KER + dx], kw[dx], a1);
            }
        }
        outp[pbase + (size_t)c * HWD] = a0;
        outp[pbase + WW + (size_t)c * HWD] = a1;
    }
}

// ---------------- residual + LayerNorm2d (over channel dim) ----------------
__global__ __launch_bounds__(256)
void ln_kernel(const float* __restrict__ fc, const float* __restrict__ res,
               const float* __restrict__ lnw, const float* __restrict__ lnb,
               float* __restrict__ out)
{
    int p = blockIdx.x * 256 + threadIdx.x;   // 0 .. B*HWD-1
    int b = p / HWD;
    int pp = p - b * HWD;
    const float* f = fc + (size_t)b * CC * HWD + pp;
    const float* r = res + (size_t)b * CC * HWD + pp;

    float s = 0.f, s2 = 0.f;
#pragma unroll 4
    for (int c = 0; c < CC; c++) {
        float v = f[(size_t)c * HWD] + r[(size_t)c * HWD];
        s += v;
        s2 = fmaf(v, v, s2);
    }
    float mu = s * (1.f / CC);
    float var = s2 * (1.f / CC) - mu * mu;
    float inv = rsqrtf(var + LN_EPS);

    float* o = out + (size_t)b * CC * HWD + pp;
#pragma unroll 4
    for (int c = 0; c < CC; c++) {
        float v = f[(size_t)c * HWD] + r[(size_t)c * HWD];
        o[(size_t)c * HWD] = lnw[c] * ((v - mu) * inv) + lnb[c];
    }
}

// ---------------- launch ----------------
extern "C" void kernel_launch(void* const* d_in, const int* in_sizes, int n_in,
                              void* d_out, int out_size)
{
    const float* q   = (const float*)d_in[0];
    const float* k   = (const float*)d_in[1];
    const float* v   = (const float*)d_in[2];
    const float* Wq  = (const float*)d_in[3];
    const float* Wk  = (const float*)d_in[4];
    const float* Wv  = (const float*)d_in[5];
    const float* Wfc = (const float*)d_in[6];
    const float* lnw = (const float*)d_in[7];
    const float* lnb = (const float*)d_in[8];

    float *qh, *kh, *vh, *att;
    cudaGetSymbolAddress((void**)&qh, g_qh);
    cudaGetSymbolAddress((void**)&kh, g_kh);
    cudaGetSymbolAddress((void**)&vh, g_vh);
    cudaGetSymbolAddress((void**)&att, g_att);
    float* fcb = qh;  // reuse q-proj scratch for FC output (qh dead after attention)

    int gemm_smem = 2 * (16 * 128 * 8 + 16 * 128 * 4);   // 48KB
    cudaFuncSetAttribute(gemm_kernel, cudaFuncAttributeMaxDynamicSharedMemorySize, gemm_smem);

    // 1) projections: [512,256] x [256,16384] per batch
    dim3 gp(HWD / 128, CO / 128, BB);
    gemm_kernel<<<gp, 256, gemm_smem>>>(Wq, q, qh, CO, CC);
    gemm_kernel<<<gp, 256, gemm_smem>>>(Wk, k, kh, CO, CC);
    gemm_kernel<<<gp, 256, gemm_smem>>>(Wv, v, vh, CO, CC);

    // 2) local attention
    int smem = DK * ANPOS * (int)sizeof(float);  // 214KB (k then v, phase-split)
    cudaFuncSetAttribute(attn_kernel, cudaFuncAttributeMaxDynamicSharedMemorySize, smem);
    dim3 ga(WW / ATW, HH / ATH, BB * NHEAD);
    attn_kernel<<<ga, 256, smem>>>(qh, kh, vh, att);

    // 3) output projection: [256,512] x [512,16384] per batch
    dim3 gf(HWD / 128, CC / 128, BB);
    gemm_kernel<<<gf, 256, gemm_smem>>>(Wfc, att, fcb, CC, CO);

    // 4) residual + LayerNorm over channels
    ln_kernel<<<(BB * HWD) / 256, 256>>>(fcb, q, lnw, lnb, (float*)d_out);
}